// round 12
// baseline (speedup 1.0000x reference)
#include <cuda_runtime.h>
#include <cuda_bf16.h>
#include <math.h>
#include <stdint.h>

typedef __nv_bfloat16 bf16;

// Shapes: B=32, N=1024, D=512, E=1024, S=128
#define ROWS 32768
#define DD   512
#define EE   1024
#define SS   128
#define NB   32
#define NN   1024
#define UVC  2176

// -------------------- scratch: pre-split bf16 planes --------------------
__device__ bf16 g_xs_h[(size_t)ROWS * DD];
__device__ bf16 g_xs_l[(size_t)ROWS * DD];
__device__ bf16 g_uvwt_h[(size_t)UVC * DD];    // uv_w^T  [2176][512]
__device__ bf16 g_uvwt_l[(size_t)UVC * DD];
__device__ bf16 g_owt_h[(size_t)DD * EE];      // o_w^T   [512][1024]
__device__ bf16 g_owt_l[(size_t)DD * EE];
__device__ float g_u[(size_t)ROWS * EE];
__device__ bf16 g_q_h[(size_t)ROWS * SS];
__device__ bf16 g_q_l[(size_t)ROWS * SS];
__device__ bf16 g_k_h[(size_t)ROWS * SS];
__device__ bf16 g_k_l[(size_t)ROWS * SS];
__device__ bf16 g_attn_h[(size_t)NB * NN * NN];
__device__ bf16 g_attn_l[(size_t)NB * NN * NN];
__device__ bf16 g_vt_h[(size_t)NB * EE * NN];  // v^T [b][e][n]
__device__ bf16 g_vt_l[(size_t)NB * EE * NN];
__device__ bf16 g_mid_h[(size_t)ROWS * EE];
__device__ bf16 g_mid_l[(size_t)ROWS * EE];

// -------------------- PTX helpers --------------------
__device__ __forceinline__ uint32_t smem_u32(const void* p) {
    return (uint32_t)__cvta_generic_to_shared(p);
}
__device__ __forceinline__ void ldsm_x4(uint32_t* r, uint32_t addr) {
    asm volatile("ldmatrix.sync.aligned.m8n8.x4.shared.b16 {%0,%1,%2,%3}, [%4];"
        : "=r"(r[0]), "=r"(r[1]), "=r"(r[2]), "=r"(r[3]) : "r"(addr));
}
__device__ __forceinline__ void mma_bf16(float* d, const uint32_t* a, const uint32_t* b) {
    asm volatile("mma.sync.aligned.m16n8k16.row.col.f32.bf16.bf16.f32 "
        "{%0,%1,%2,%3}, {%4,%5,%6,%7}, {%8,%9}, {%0,%1,%2,%3};"
        : "+f"(d[0]), "+f"(d[1]), "+f"(d[2]), "+f"(d[3])
        : "r"(a[0]), "r"(a[1]), "r"(a[2]), "r"(a[3]), "r"(b[0]), "r"(b[1]));
}
#define CP16(d, s)  asm volatile("cp.async.cg.shared.global [%0], [%1], 16;" :: "r"(d), "l"(s))
#define CP_COMMIT() asm volatile("cp.async.commit_group;" ::: "memory")
#define CP_WAIT(n)  asm volatile("cp.async.wait_group %0;" :: "n"(n) : "memory")

__device__ __forceinline__ uint32_t pk2(bf16 a, bf16 b) {
    return (uint32_t)__bfloat16_as_ushort(a) | ((uint32_t)__bfloat16_as_ushort(b) << 16);
}
__device__ __forceinline__ void split2(float f, bf16& h, bf16& l) {
    h = __float2bfloat16(f);
    l = __float2bfloat16(f - __bfloat162float(h));
}
__device__ __forceinline__ uint32_t pksplit(float a, float b, uint32_t& lo) {
    bf16 h0, l0, h1, l1;
    split2(a, h0, l0); split2(b, h1, l1);
    lo = pk2(l0, l1);
    return pk2(h0, h1);
}

// -------------------- prep kernels --------------------
__global__ __launch_bounds__(256) void rownorm_split(const float* __restrict__ x,
                                                     const float* __restrict__ gptr)
{
    int row  = blockIdx.x * 8 + (threadIdx.x >> 5);
    int lane = threadIdx.x & 31;
    const float* xr = x + (size_t)row * DD;
    float vbuf[16];
    float s = 0.f;
#pragma unroll
    for (int t = 0; t < 16; t++) {
        vbuf[t] = xr[lane + 32 * t];
        s = fmaf(vbuf[t], vbuf[t], s);
    }
#pragma unroll
    for (int o = 16; o; o >>= 1) s += __shfl_xor_sync(0xffffffffu, s, o);
    float sc = gptr[0] / fmaxf(sqrtf(s), 1e-5f);
#pragma unroll
    for (int t = 0; t < 16; t++) {
        bf16 h, l; split2(vbuf[t] * sc, h, l);
        size_t idx = (size_t)row * DD + lane + 32 * t;
        g_xs_h[idx] = h;
        g_xs_l[idx] = l;
    }
}
template<int W>
__global__ __launch_bounds__(256) void wsplit(const float* __restrict__ src)
{
    int id = blockIdx.x * 256 + threadIdx.x;
    if (W == 0) {
        if (id >= UVC * DD) return;
        int c = id / DD, r = id % DD;
        bf16 h, l; split2(src[(size_t)r * UVC + c], h, l);
        g_uvwt_h[id] = h; g_uvwt_l[id] = l;
    } else {
        if (id >= DD * EE) return;
        int e = id % EE, d = id / EE;
        bf16 h, l; split2(src[(size_t)e * DD + d], h, l);
        g_owt_h[id] = h; g_owt_l[id] = l;
    }
}

// ==========================================================================
// mma.sync bf16x3 GEMM, pre-split operands, cp.async 1-barrier pipeline.
// 1 CTA/SM, unbounded regs (no spills), 2-deep FRAGMENT pipeline: both
// ks-steps' fragments loaded before/while MMA phases run -> LDSM latency
// hidden under 48 MMAs instead of heading each phase.
// 128x128 CTA tile, BK=32, 8 warps (2x4), warp 64x32 = 4x4 m16n8k16 grid.
// MODE 0: uv (A=xs, B=uvwt, K=512)   epi: silu -> u / vt(staged) / q,k
// MODE 1: qk (A=q,  B=k,    K=128)   epi: +bias, relu^2/sqrtS -> attn
// MODE 2: av (A=attn, B=vt, K=1024)  epi: u-gate -> mid
// MODE 3: fin(A=mid,  B=owt,K=1024)  epi: residual -> out
// ==========================================================================
#define LDA      40                      // elems per smem row (80 B, conflict-free)
#define PLANE_BY (128 * LDA * 2)         // 10240
#define BUF_BY   (4 * PLANE_BY)          // 40960
#define SMEM_SZ  (2 * BUF_BY)            // 81920

struct Frags {
    uint32_t bhi[4][2], blo[4][2];
    uint32_t ahi[4][4], alo[4][4];
};

__device__ __forceinline__ void load_frags(Frags& f,
    uint32_t uAh, uint32_t uAl, uint32_t uBh, uint32_t uBl,
    int warp_m, int warp_n, int lane, int ks)
{
#pragma unroll
    for (int p = 0; p < 2; p++) {
        int n = warp_n * 32 + p * 16 + (lane & 7) + ((lane >> 4) << 3);
        uint32_t off = (uint32_t)(n * LDA + ks + (((lane >> 3) & 1) << 3)) * 2;
        uint32_t r4[4];
        ldsm_x4(r4, uBh + off);
        f.bhi[2*p][0] = r4[0]; f.bhi[2*p][1] = r4[1];
        f.bhi[2*p+1][0] = r4[2]; f.bhi[2*p+1][1] = r4[3];
        ldsm_x4(r4, uBl + off);
        f.blo[2*p][0] = r4[0]; f.blo[2*p][1] = r4[1];
        f.blo[2*p+1][0] = r4[2]; f.blo[2*p+1][1] = r4[3];
    }
#pragma unroll
    for (int mt = 0; mt < 4; mt++) {
        int m = warp_m * 64 + mt * 16 + (lane & 15);
        uint32_t off = (uint32_t)(m * LDA + ks + ((lane >> 4) << 3)) * 2;
        ldsm_x4(f.ahi[mt], uAh + off);
        ldsm_x4(f.alo[mt], uAl + off);
    }
}

__device__ __forceinline__ void mma_all(float acc[4][4][4], const Frags& f)
{
#pragma unroll
    for (int mt = 0; mt < 4; mt++)
#pragma unroll
        for (int nt = 0; nt < 4; nt++)
            mma_bf16(acc[mt][nt], f.ahi[mt], f.bhi[nt]);
#pragma unroll
    for (int mt = 0; mt < 4; mt++)
#pragma unroll
        for (int nt = 0; nt < 4; nt++)
            mma_bf16(acc[mt][nt], f.ahi[mt], f.blo[nt]);
#pragma unroll
    for (int mt = 0; mt < 4; mt++)
#pragma unroll
        for (int nt = 0; nt < 4; nt++)
            mma_bf16(acc[mt][nt], f.alo[mt], f.bhi[nt]);
}

template<int MODE>
__global__ __launch_bounds__(256) void gemm12(
    const float* __restrict__ e0, const float* __restrict__ e1, float* __restrict__ outp)
{
    constexpr int K      = (MODE == 0) ? DD : (MODE == 1) ? SS : NN;
    constexpr int CHUNKS = K / 32;

    extern __shared__ char smem[];
    const uint32_t sbase = smem_u32(smem);
    const int tid = threadIdx.x, wid = tid >> 5, lane = tid & 31;
    const int warp_m = wid >> 2, warp_n = wid & 3;
    const int bx = blockIdx.x, b = blockIdx.z;
    const int row0 = blockIdx.y * 128, col0 = bx * 128;

    const bf16 *planes[4];
    if (MODE == 0) { planes[0] = g_xs_h;   planes[1] = g_xs_l;
                     planes[2] = g_uvwt_h; planes[3] = g_uvwt_l; }
    if (MODE == 1) { planes[0] = g_q_h + (size_t)b * NN * SS;  planes[1] = g_q_l + (size_t)b * NN * SS;
                     planes[2] = g_k_h + (size_t)b * NN * SS;  planes[3] = g_k_l + (size_t)b * NN * SS; }
    if (MODE == 2) { planes[0] = g_attn_h + (size_t)b * NN * NN; planes[1] = g_attn_l + (size_t)b * NN * NN;
                     planes[2] = g_vt_h + (size_t)b * EE * NN;   planes[3] = g_vt_l + (size_t)b * EE * NN; }
    if (MODE == 3) { planes[0] = g_mid_h;  planes[1] = g_mid_l;
                     planes[2] = g_owt_h;  planes[3] = g_owt_l; }

    // per-thread load coords: 2 x 16B per plane
    const int lr0 = tid >> 2, lc0 = tid & 3;
    const int lr1 = lr0 + 64;

    float acc[4][4][4];
#pragma unroll
    for (int i = 0; i < 4; i++)
#pragma unroll
        for (int j = 0; j < 4; j++)
#pragma unroll
            for (int e = 0; e < 4; e++) acc[i][j][e] = 0.f;

    auto load_chunk = [&](int c, int buf) {
        const uint32_t bo = sbase + buf * BUF_BY;
        const int k0 = c * 32;
#pragma unroll
        for (int p = 0; p < 4; p++) {
            const bf16* src = planes[p] + k0;
            const int rbase = (p < 2) ? row0 : col0;
            CP16(bo + p * PLANE_BY + lr0 * 80 + lc0 * 16,
                 src + (size_t)(rbase + lr0) * K + lc0 * 8);
            CP16(bo + p * PLANE_BY + lr1 * 80 + lc0 * 16,
                 src + (size_t)(rbase + lr1) * K + lc0 * 8);
        }
        CP_COMMIT();
    };

    load_chunk(0, 0);

    for (int c = 0; c < CHUNKS; c++) {
        CP_WAIT(0);            // chunk c's loads (only pending group) complete
        __syncthreads();       // also proves all warps done reading buffer (c+1)&1

        const uint32_t bo = sbase + (c & 1) * BUF_BY;
        const uint32_t uAh = bo, uAl = bo + PLANE_BY;
        const uint32_t uBh = bo + 2 * PLANE_BY, uBl = bo + 3 * PLANE_BY;

        Frags f0, f1;
        load_frags(f0, uAh, uAl, uBh, uBl, warp_m, warp_n, lane, 0);
        if (c + 1 < CHUNKS) load_chunk(c + 1, (c + 1) & 1);   // overlaps compute below
        load_frags(f1, uAh, uAl, uBh, uBl, warp_m, warp_n, lane, 16);
        mma_all(acc, f0);      // runs while f1's LDSMs are still in flight
        mma_all(acc, f1);
        // no trailing barrier: next iteration's barrier provides the guarantee
    }

    // -------------------- epilogue --------------------
    const float inv_sqrt_s = 0.088388347648318447f;   // 1/sqrt(128)
    bf16* stH = (bf16*)smem;                          // v-transpose staging (aliased)
    bf16* stL = (bf16*)(smem + 128 * 136 * 2);
    if (MODE == 0) __syncthreads();                   // staging aliases pipeline buffers

#pragma unroll
    for (int mt = 0; mt < 4; mt++) {
#pragma unroll
        for (int nt = 0; nt < 4; nt++) {
            int mb = row0 + warp_m * 64 + mt * 16 + (lane >> 2);
            int nb = col0 + warp_n * 32 + nt * 8 + ((lane & 3) << 1);
#pragma unroll
            for (int h = 0; h < 2; h++) {
                int m = mb + 8 * h;
                int n = nb;
                float v0 = acc[mt][nt][h * 2 + 0];
                float v1 = acc[mt][nt][h * 2 + 1];
                if (MODE == 0) {
                    float s0 = v0 / (1.f + __expf(-v0));
                    float s1 = v1 / (1.f + __expf(-v1));
                    if (bx < 8) {                      // u (fp32)
                        *(float2*)(g_u + (size_t)m * EE + n) = make_float2(s0, s1);
                    } else if (bx < 16) {              // v -> stage transposed split
                        bf16 h0, l0, h1, l1;
                        split2(s0, h0, l0); split2(s1, h1, l1);
                        int nl = n - col0, ml = m - row0;
                        stH[nl * 136 + ml] = h0;       stL[nl * 136 + ml] = l0;
                        stH[(nl + 1) * 136 + ml] = h1; stL[(nl + 1) * 136 + ml] = l1;
                    } else {                           // q,k split
                        int s = n - 2 * EE;
                        uint32_t lo, hi;
                        size_t o = (size_t)m * SS + s;
                        hi = pksplit(fmaf(s0, e0[s], e1[s]), fmaf(s1, e0[s + 1], e1[s + 1]), lo);
                        *(uint32_t*)(g_q_h + o) = hi; *(uint32_t*)(g_q_l + o) = lo;
                        hi = pksplit(fmaf(s0, e0[SS + s], e1[SS + s]),
                                     fmaf(s1, e0[SS + s + 1], e1[SS + s + 1]), lo);
                        *(uint32_t*)(g_k_h + o) = hi; *(uint32_t*)(g_k_l + o) = lo;
                    }
                } else if (MODE == 1) {
                    float t0 = (v0 + e0[NN - 1 + n - m]) * inv_sqrt_s;     t0 = fmaxf(t0, 0.f);
                    float t1 = (v1 + e0[NN - 1 + n + 1 - m]) * inv_sqrt_s; t1 = fmaxf(t1, 0.f);
                    uint32_t lo, hi = pksplit(t0 * t0, t1 * t1, lo);
                    size_t o = ((size_t)b * NN + m) * NN + n;
                    *(uint32_t*)(g_attn_h + o) = hi;
                    *(uint32_t*)(g_attn_l + o) = lo;
                } else if (MODE == 2) {
                    size_t o = ((size_t)b * NN + m) * EE + n;
                    float2 uu = *(const float2*)(g_u + o);
                    uint32_t lo, hi = pksplit(uu.x * v0, uu.y * v1, lo);
                    *(uint32_t*)(g_mid_h + o) = hi;
                    *(uint32_t*)(g_mid_l + o) = lo;
                } else {
                    size_t o = (size_t)m * DD + n;
                    float2 xv = *(const float2*)(e0 + o);
                    *(float2*)(outp + o) = make_float2(fmaf(xv.x, e1[n], v0),
                                                       fmaf(xv.y, e1[n + 1], v1));
                }
            }
        }
    }

    // v-block: coalesced copy-out of staged transposed tile
    if (MODE == 0 && bx >= 8 && bx < 16) {
        __syncthreads();
        const int bb = row0 >> 10, mloc = row0 & (NN - 1);
        const int ebase = col0 - EE;
#pragma unroll
        for (int it = 0; it < 8; it++) {
            int id = tid + 256 * it;
            int el = id >> 4, mw = id & 15;
            size_t o = ((size_t)bb * EE + ebase + el) * NN + mloc + mw * 8;
            *(uint4*)(g_vt_h + o) = *(const uint4*)&stH[el * 136 + mw * 8];
            *(uint4*)(g_vt_l + o) = *(const uint4*)&stL[el * 136 + mw * 8];
        }
    }
}

// -------------------- launch --------------------
extern "C" void kernel_launch(void* const* d_in, const int* in_sizes, int n_in,
                              void* d_out, int out_size)
{
    const float* x     = (const float*)d_in[0];
    const float* w     = (const float*)d_in[1];
    const float* uvw   = (const float*)d_in[2];
    const float* ow    = (const float*)d_in[3];
    const float* gamma = (const float*)d_in[4];
    const float* beta  = (const float*)d_in[5];
    const float* g     = (const float*)d_in[6];
    const float* res   = (const float*)d_in[7];
    float* out = (float*)d_out;

    cudaFuncSetAttribute(gemm12<0>, cudaFuncAttributeMaxDynamicSharedMemorySize, SMEM_SZ);
    cudaFuncSetAttribute(gemm12<1>, cudaFuncAttributeMaxDynamicSharedMemorySize, SMEM_SZ);
    cudaFuncSetAttribute(gemm12<2>, cudaFuncAttributeMaxDynamicSharedMemorySize, SMEM_SZ);
    cudaFuncSetAttribute(gemm12<3>, cudaFuncAttributeMaxDynamicSharedMemorySize, SMEM_SZ);

    rownorm_split<<<ROWS / 8, 256>>>(x, g);
    wsplit<0><<<(UVC * DD + 255) / 256, 256>>>(uvw);
    wsplit<1><<<(DD * EE + 255) / 256, 256>>>(ow);

    gemm12<0><<<dim3(UVC / 128, ROWS / 128, 1), 256, SMEM_SZ>>>(gamma, beta, nullptr);
    gemm12<1><<<dim3(NN / 128, NN / 128, NB),   256, SMEM_SZ>>>(w, nullptr, nullptr);
    gemm12<2><<<dim3(EE / 128, NN / 128, NB),   256, SMEM_SZ>>>(nullptr, nullptr, nullptr);
    gemm12<3><<<dim3(DD / 128, ROWS / 128, 1),  256, SMEM_SZ>>>(x, res, out);
}

// round 13
// speedup vs baseline: 1.1554x; 1.1554x over previous
#include <cuda_runtime.h>
#include <cuda_bf16.h>
#include <math.h>
#include <stdint.h>

typedef __nv_bfloat16 bf16;

// Shapes: B=32, N=1024, D=512, E=1024, S=128
#define ROWS 32768
#define DD   512
#define EE   1024
#define SS   128
#define NB   32
#define NN   1024
#define UVC  2176

// -------------------- scratch: pre-split bf16 planes --------------------
__device__ bf16 g_xs_h[(size_t)ROWS * DD];
__device__ bf16 g_xs_l[(size_t)ROWS * DD];
__device__ bf16 g_uvwt_h[(size_t)UVC * DD];    // uv_w^T  [2176][512]
__device__ bf16 g_uvwt_l[(size_t)UVC * DD];
__device__ bf16 g_owt_h[(size_t)DD * EE];      // o_w^T   [512][1024]
__device__ bf16 g_owt_l[(size_t)DD * EE];
__device__ float g_u[(size_t)ROWS * EE];
__device__ bf16 g_q_h[(size_t)ROWS * SS];
__device__ bf16 g_q_l[(size_t)ROWS * SS];
__device__ bf16 g_k_h[(size_t)ROWS * SS];
__device__ bf16 g_k_l[(size_t)ROWS * SS];
__device__ bf16 g_attn_h[(size_t)NB * NN * NN];
__device__ bf16 g_attn_l[(size_t)NB * NN * NN];
__device__ bf16 g_vt_h[(size_t)NB * EE * NN];  // v^T [b][e][n]
__device__ bf16 g_vt_l[(size_t)NB * EE * NN];
__device__ bf16 g_mid_h[(size_t)ROWS * EE];
__device__ bf16 g_mid_l[(size_t)ROWS * EE];

// -------------------- PTX helpers --------------------
__device__ __forceinline__ uint32_t smem_u32(const void* p) {
    return (uint32_t)__cvta_generic_to_shared(p);
}
__device__ __forceinline__ void ldsm_x4(uint32_t* r, uint32_t addr) {
    asm volatile("ldmatrix.sync.aligned.m8n8.x4.shared.b16 {%0,%1,%2,%3}, [%4];"
        : "=r"(r[0]), "=r"(r[1]), "=r"(r[2]), "=r"(r[3]) : "r"(addr));
}
__device__ __forceinline__ void mma_bf16(float* d, const uint32_t* a, const uint32_t* b) {
    asm volatile("mma.sync.aligned.m16n8k16.row.col.f32.bf16.bf16.f32 "
        "{%0,%1,%2,%3}, {%4,%5,%6,%7}, {%8,%9}, {%0,%1,%2,%3};"
        : "+f"(d[0]), "+f"(d[1]), "+f"(d[2]), "+f"(d[3])
        : "r"(a[0]), "r"(a[1]), "r"(a[2]), "r"(a[3]), "r"(b[0]), "r"(b[1]));
}
#define CP16(d, s)  asm volatile("cp.async.cg.shared.global [%0], [%1], 16;" :: "r"(d), "l"(s))
#define CP_COMMIT() asm volatile("cp.async.commit_group;" ::: "memory")
#define CP_WAIT(n)  asm volatile("cp.async.wait_group %0;" :: "n"(n) : "memory")

__device__ __forceinline__ uint32_t pk2(bf16 a, bf16 b) {
    return (uint32_t)__bfloat16_as_ushort(a) | ((uint32_t)__bfloat16_as_ushort(b) << 16);
}
__device__ __forceinline__ void split2(float f, bf16& h, bf16& l) {
    h = __float2bfloat16(f);
    l = __float2bfloat16(f - __bfloat162float(h));
}
__device__ __forceinline__ uint32_t pksplit(float a, float b, uint32_t& lo) {
    bf16 h0, l0, h1, l1;
    split2(a, h0, l0); split2(b, h1, l1);
    lo = pk2(l0, l1);
    return pk2(h0, h1);
}

// -------------------- prep kernels --------------------
__global__ __launch_bounds__(256) void rownorm_split(const float* __restrict__ x,
                                                     const float* __restrict__ gptr)
{
    int row  = blockIdx.x * 8 + (threadIdx.x >> 5);
    int lane = threadIdx.x & 31;
    const float* xr = x + (size_t)row * DD;
    float vbuf[16];
    float s = 0.f;
#pragma unroll
    for (int t = 0; t < 16; t++) {
        vbuf[t] = xr[lane + 32 * t];
        s = fmaf(vbuf[t], vbuf[t], s);
    }
#pragma unroll
    for (int o = 16; o; o >>= 1) s += __shfl_xor_sync(0xffffffffu, s, o);
    float sc = gptr[0] / fmaxf(sqrtf(s), 1e-5f);
#pragma unroll
    for (int t = 0; t < 16; t++) {
        bf16 h, l; split2(vbuf[t] * sc, h, l);
        size_t idx = (size_t)row * DD + lane + 32 * t;
        g_xs_h[idx] = h;
        g_xs_l[idx] = l;
    }
}
template<int W>
__global__ __launch_bounds__(256) void wsplit(const float* __restrict__ src)
{
    int id = blockIdx.x * 256 + threadIdx.x;
    if (W == 0) {
        if (id >= UVC * DD) return;
        int c = id / DD, r = id % DD;
        bf16 h, l; split2(src[(size_t)r * UVC + c], h, l);
        g_uvwt_h[id] = h; g_uvwt_l[id] = l;
    } else {
        if (id >= DD * EE) return;
        int e = id % EE, d = id / EE;
        bf16 h, l; split2(src[(size_t)e * DD + d], h, l);
        g_owt_h[id] = h; g_owt_l[id] = l;
    }
}

// ==========================================================================
// mma.sync bf16x3 GEMM, pre-split operands, cp.async 1-barrier pipeline.
// 3 CTAs/SM (85-reg cap): CTA tile 128x64, 8 warps (4x2), warp tile 32x32
// = 2x4 grid of m16n8k16.  Independent per-CTA barriers cover each other's
// pipeline stalls on the shared tensor pipe.
// MODE 0: uv (A=xs, B=uvwt, K=512)   epi: silu -> u / vt(staged) / q,k
// MODE 1: qk (A=q,  B=k,    K=128)   epi: +bias, relu^2/sqrtS -> attn
// MODE 2: av (A=attn, B=vt, K=1024)  epi: u-gate -> mid
// MODE 3: fin(A=mid,  B=owt,K=1024)  epi: residual -> out
// ==========================================================================
#define LDA       40                     // elems per smem row (80 B, conflict-free)
#define APLANE_BY (128 * LDA * 2)        // 10240
#define BPLANE_BY (64  * LDA * 2)        // 5120
#define BUF_BY    (2 * APLANE_BY + 2 * BPLANE_BY)   // 30720
#define SMEM_SZ   (2 * BUF_BY)                      // 61440

template<int MODE>
__global__ __launch_bounds__(256, 3) void gemm13(
    const float* __restrict__ e0, const float* __restrict__ e1, float* __restrict__ outp)
{
    constexpr int K      = (MODE == 0) ? DD : (MODE == 1) ? SS : NN;
    constexpr int CHUNKS = K / 32;

    extern __shared__ char smem[];
    const uint32_t sbase = smem_u32(smem);
    const int tid = threadIdx.x, wid = tid >> 5, lane = tid & 31;
    const int warp_m = wid >> 1, warp_n = wid & 1;   // 4 x 2 warp grid
    const int bx = blockIdx.x, b = blockIdx.z;
    const int row0 = blockIdx.y * 128, col0 = bx * 64;

    const bf16 *planes[4];
    if (MODE == 0) { planes[0] = g_xs_h;   planes[1] = g_xs_l;
                     planes[2] = g_uvwt_h; planes[3] = g_uvwt_l; }
    if (MODE == 1) { planes[0] = g_q_h + (size_t)b * NN * SS;  planes[1] = g_q_l + (size_t)b * NN * SS;
                     planes[2] = g_k_h + (size_t)b * NN * SS;  planes[3] = g_k_l + (size_t)b * NN * SS; }
    if (MODE == 2) { planes[0] = g_attn_h + (size_t)b * NN * NN; planes[1] = g_attn_l + (size_t)b * NN * NN;
                     planes[2] = g_vt_h + (size_t)b * EE * NN;   planes[3] = g_vt_l + (size_t)b * EE * NN; }
    if (MODE == 3) { planes[0] = g_mid_h;  planes[1] = g_mid_l;
                     planes[2] = g_owt_h;  planes[3] = g_owt_l; }

    // per-thread cp.async coords: A planes 2x16B (rows lr0, lr0+64), B planes 1x16B
    const int lr0 = tid >> 2, lc0 = tid & 3;
    const int lr1 = lr0 + 64;

    float acc[2][4][4];
#pragma unroll
    for (int i = 0; i < 2; i++)
#pragma unroll
        for (int j = 0; j < 4; j++)
#pragma unroll
            for (int e = 0; e < 4; e++) acc[i][j][e] = 0.f;

    auto load_chunk = [&](int c, int buf) {
        const uint32_t bo = sbase + buf * BUF_BY;
        const int k0 = c * 32;
#pragma unroll
        for (int p = 0; p < 2; p++) {   // A hi/lo: 128 rows
            const bf16* src = planes[p] + k0;
            CP16(bo + p * APLANE_BY + lr0 * 80 + lc0 * 16,
                 src + (size_t)(row0 + lr0) * K + lc0 * 8);
            CP16(bo + p * APLANE_BY + lr1 * 80 + lc0 * 16,
                 src + (size_t)(row0 + lr1) * K + lc0 * 8);
        }
#pragma unroll
        for (int p = 0; p < 2; p++) {   // B hi/lo: 64 rows
            const bf16* src = planes[2 + p] + k0;
            CP16(bo + 2 * APLANE_BY + p * BPLANE_BY + lr0 * 80 + lc0 * 16,
                 src + (size_t)(col0 + lr0) * K + lc0 * 8);
        }
        CP_COMMIT();
    };

    load_chunk(0, 0);

    for (int c = 0; c < CHUNKS; c++) {
        CP_WAIT(0);            // chunk c's loads (only pending group) complete
        __syncthreads();       // also proves all warps done reading buffer (c+1)&1
        if (c + 1 < CHUNKS) load_chunk(c + 1, (c + 1) & 1);   // overlaps compute below

        const uint32_t bo = sbase + (c & 1) * BUF_BY;
        const uint32_t uAh = bo, uAl = bo + APLANE_BY;
        const uint32_t uBh = bo + 2 * APLANE_BY, uBl = uBh + BPLANE_BY;

#pragma unroll
        for (int ks = 0; ks < 32; ks += 16) {
            // B fragments: 2 p-groups of 16 n -> 4 n8 tiles, hi+lo
            uint32_t bhi[4][2], blo[4][2];
#pragma unroll
            for (int p = 0; p < 2; p++) {
                int n = warp_n * 32 + p * 16 + (lane & 7) + ((lane >> 4) << 3);
                uint32_t off = (uint32_t)(n * LDA + ks + (((lane >> 3) & 1) << 3)) * 2;
                uint32_t r4[4];
                ldsm_x4(r4, uBh + off);
                bhi[2*p][0] = r4[0]; bhi[2*p][1] = r4[1];
                bhi[2*p+1][0] = r4[2]; bhi[2*p+1][1] = r4[3];
                ldsm_x4(r4, uBl + off);
                blo[2*p][0] = r4[0]; blo[2*p][1] = r4[1];
                blo[2*p+1][0] = r4[2]; blo[2*p+1][1] = r4[3];
            }
#pragma unroll
            for (int mt = 0; mt < 2; mt++) {
                int m = warp_m * 32 + mt * 16 + (lane & 15);
                uint32_t off = (uint32_t)(m * LDA + ks + ((lane >> 4) << 3)) * 2;
                uint32_t ahi[4], alo[4];
                ldsm_x4(ahi, uAh + off);
                ldsm_x4(alo, uAl + off);
#pragma unroll
                for (int nt = 0; nt < 4; nt++) {
                    mma_bf16(acc[mt][nt], ahi, bhi[nt]);
                    mma_bf16(acc[mt][nt], ahi, blo[nt]);
                    mma_bf16(acc[mt][nt], alo, bhi[nt]);
                }
            }
        }
        // no trailing barrier: next iteration's barrier provides the guarantee
    }

    // -------------------- epilogue --------------------
    const float inv_sqrt_s = 0.088388347648318447f;   // 1/sqrt(128)
    bf16* stH = (bf16*)smem;                          // v-transpose staging (aliased)
    bf16* stL = (bf16*)(smem + 64 * 136 * 2);         // 64 nl x 136(128 ml + pad)
    if (MODE == 0) __syncthreads();                   // staging aliases pipeline buffers

#pragma unroll
    for (int mt = 0; mt < 2; mt++) {
#pragma unroll
        for (int nt = 0; nt < 4; nt++) {
            int mb = row0 + warp_m * 32 + mt * 16 + (lane >> 2);
            int nb = col0 + warp_n * 32 + nt * 8 + ((lane & 3) << 1);
#pragma unroll
            for (int h = 0; h < 2; h++) {
                int m = mb + 8 * h;
                int n = nb;
                float v0 = acc[mt][nt][h * 2 + 0];
                float v1 = acc[mt][nt][h * 2 + 1];
                if (MODE == 0) {
                    float s0 = v0 / (1.f + __expf(-v0));
                    float s1 = v1 / (1.f + __expf(-v1));
                    if (bx < 16) {                     // u (fp32)
                        *(float2*)(g_u + (size_t)m * EE + n) = make_float2(s0, s1);
                    } else if (bx < 32) {              // v -> stage transposed split
                        bf16 h0, l0, h1, l1;
                        split2(s0, h0, l0); split2(s1, h1, l1);
                        int nl = n - col0, ml = m - row0;
                        stH[nl * 136 + ml] = h0;       stL[nl * 136 + ml] = l0;
                        stH[(nl + 1) * 136 + ml] = h1; stL[(nl + 1) * 136 + ml] = l1;
                    } else {                           // q,k split
                        int s = n - 2 * EE;
                        uint32_t lo, hi;
                        size_t o = (size_t)m * SS + s;
                        hi = pksplit(fmaf(s0, e0[s], e1[s]), fmaf(s1, e0[s + 1], e1[s + 1]), lo);
                        *(uint32_t*)(g_q_h + o) = hi; *(uint32_t*)(g_q_l + o) = lo;
                        hi = pksplit(fmaf(s0, e0[SS + s], e1[SS + s]),
                                     fmaf(s1, e0[SS + s + 1], e1[SS + s + 1]), lo);
                        *(uint32_t*)(g_k_h + o) = hi; *(uint32_t*)(g_k_l + o) = lo;
                    }
                } else if (MODE == 1) {
                    float t0 = (v0 + e0[NN - 1 + n - m]) * inv_sqrt_s;     t0 = fmaxf(t0, 0.f);
                    float t1 = (v1 + e0[NN - 1 + n + 1 - m]) * inv_sqrt_s; t1 = fmaxf(t1, 0.f);
                    uint32_t lo, hi = pksplit(t0 * t0, t1 * t1, lo);
                    size_t o = ((size_t)b * NN + m) * NN + n;
                    *(uint32_t*)(g_attn_h + o) = hi;
                    *(uint32_t*)(g_attn_l + o) = lo;
                } else if (MODE == 2) {
                    size_t o = ((size_t)b * NN + m) * EE + n;
                    float2 uu = *(const float2*)(g_u + o);
                    uint32_t lo, hi = pksplit(uu.x * v0, uu.y * v1, lo);
                    *(uint32_t*)(g_mid_h + o) = hi;
                    *(uint32_t*)(g_mid_l + o) = lo;
                } else {
                    size_t o = (size_t)m * DD + n;
                    float2 xv = *(const float2*)(e0 + o);
                    *(float2*)(outp + o) = make_float2(fmaf(xv.x, e1[n], v0),
                                                       fmaf(xv.y, e1[n + 1], v1));
                }
            }
        }
    }

    // v-block: coalesced copy-out of staged transposed tile (64 e x 128 m)
    if (MODE == 0 && bx >= 16 && bx < 32) {
        __syncthreads();
        const int bb = row0 >> 10, mloc = row0 & (NN - 1);
        const int ebase = col0 - EE;
#pragma unroll
        for (int it = 0; it < 4; it++) {
            int id = tid + 256 * it;
            int el = id >> 4, mw = id & 15;
            size_t o = ((size_t)bb * EE + ebase + el) * NN + mloc + mw * 8;
            *(uint4*)(g_vt_h + o) = *(const uint4*)&stH[el * 136 + mw * 8];
            *(uint4*)(g_vt_l + o) = *(const uint4*)&stL[el * 136 + mw * 8];
        }
    }
}

// -------------------- launch --------------------
extern "C" void kernel_launch(void* const* d_in, const int* in_sizes, int n_in,
                              void* d_out, int out_size)
{
    const float* x     = (const float*)d_in[0];
    const float* w     = (const float*)d_in[1];
    const float* uvw   = (const float*)d_in[2];
    const float* ow    = (const float*)d_in[3];
    const float* gamma = (const float*)d_in[4];
    const float* beta  = (const float*)d_in[5];
    const float* g     = (const float*)d_in[6];
    const float* res   = (const float*)d_in[7];
    float* out = (float*)d_out;

    cudaFuncSetAttribute(gemm13<0>, cudaFuncAttributeMaxDynamicSharedMemorySize, SMEM_SZ);
    cudaFuncSetAttribute(gemm13<1>, cudaFuncAttributeMaxDynamicSharedMemorySize, SMEM_SZ);
    cudaFuncSetAttribute(gemm13<2>, cudaFuncAttributeMaxDynamicSharedMemorySize, SMEM_SZ);
    cudaFuncSetAttribute(gemm13<3>, cudaFuncAttributeMaxDynamicSharedMemorySize, SMEM_SZ);

    rownorm_split<<<ROWS / 8, 256>>>(x, g);
    wsplit<0><<<(UVC * DD + 255) / 256, 256>>>(uvw);
    wsplit<1><<<(DD * EE + 255) / 256, 256>>>(ow);

    gemm13<0><<<dim3(UVC / 64, ROWS / 128, 1), 256, SMEM_SZ>>>(gamma, beta, nullptr);
    gemm13<1><<<dim3(NN / 64, NN / 128, NB),   256, SMEM_SZ>>>(w, nullptr, nullptr);
    gemm13<2><<<dim3(EE / 64, NN / 128, NB),   256, SMEM_SZ>>>(nullptr, nullptr, nullptr);
    gemm13<3><<<dim3(DD / 64, ROWS / 128, 1),  256, SMEM_SZ>>>(x, res, out);
}

// round 15
// speedup vs baseline: 1.6123x; 1.3955x over previous
#include <cuda_runtime.h>
#include <cuda_fp16.h>
#include <math.h>
#include <stdint.h>

typedef __half fp16;

// Shapes: B=32, N=1024, D=512, E=1024, S=128
#define ROWS 32768
#define DD   512
#define EE   1024
#define SS   128
#define NB   32
#define NN   1024
#define UVC  2176

// -------------------- scratch: fp16 planes --------------------
// A-role operands: hi+lo split.  B-role: single fp16 (except k: qk is 3-term).
__device__ fp16 g_xs_h[(size_t)ROWS * DD];
__device__ fp16 g_xs_l[(size_t)ROWS * DD];
__device__ fp16 g_uvwt[(size_t)UVC * DD];      // uv_w^T [2176][512], single
__device__ fp16 g_owt[(size_t)DD * EE];        // o_w^T  [512][1024], single
__device__ float g_u[(size_t)ROWS * EE];
__device__ fp16 g_q_h[(size_t)ROWS * SS];
__device__ fp16 g_q_l[(size_t)ROWS * SS];
__device__ fp16 g_k_h[(size_t)ROWS * SS];      // k split: qk stays 3-term
__device__ fp16 g_k_l[(size_t)ROWS * SS];
__device__ fp16 g_attn_h[(size_t)NB * NN * NN];
__device__ fp16 g_attn_l[(size_t)NB * NN * NN];
__device__ fp16 g_vt[(size_t)NB * EE * NN];    // v^T [b][e][n], single
__device__ fp16 g_mid_h[(size_t)ROWS * EE];
__device__ fp16 g_mid_l[(size_t)ROWS * EE];

// -------------------- PTX helpers --------------------
__device__ __forceinline__ uint32_t smem_u32(const void* p) {
    return (uint32_t)__cvta_generic_to_shared(p);
}
__device__ __forceinline__ void ldsm_x4(uint32_t* r, uint32_t addr) {
    asm volatile("ldmatrix.sync.aligned.m8n8.x4.shared.b16 {%0,%1,%2,%3}, [%4];"
        : "=r"(r[0]), "=r"(r[1]), "=r"(r[2]), "=r"(r[3]) : "r"(addr));
}
__device__ __forceinline__ void mma_f16(float* d, const uint32_t* a, const uint32_t* b) {
    asm volatile("mma.sync.aligned.m16n8k16.row.col.f32.f16.f16.f32 "
        "{%0,%1,%2,%3}, {%4,%5,%6,%7}, {%8,%9}, {%0,%1,%2,%3};"
        : "+f"(d[0]), "+f"(d[1]), "+f"(d[2]), "+f"(d[3])
        : "r"(a[0]), "r"(a[1]), "r"(a[2]), "r"(a[3]), "r"(b[0]), "r"(b[1]));
}
#define CP16(d, s)  asm volatile("cp.async.cg.shared.global [%0], [%1], 16;" :: "r"(d), "l"(s))
#define CP_COMMIT() asm volatile("cp.async.commit_group;" ::: "memory")
#define CP_WAIT(n)  asm volatile("cp.async.wait_group %0;" :: "n"(n) : "memory")

__device__ __forceinline__ uint32_t pk2h(fp16 a, fp16 b) {
    return (uint32_t)__half_as_ushort(a) | ((uint32_t)__half_as_ushort(b) << 16);
}
__device__ __forceinline__ void split2h(float f, fp16& h, fp16& l) {
    h = __float2half_rn(f);
    l = __float2half_rn(f - __half2float(h));
}
// pack split of (a,b): returns hi-pair, sets lo-pair
__device__ __forceinline__ uint32_t pksplit_h(float a, float b, uint32_t& lo) {
    fp16 h0, l0, h1, l1;
    split2h(a, h0, l0); split2h(b, h1, l1);
    lo = pk2h(l0, l1);
    return pk2h(h0, h1);
}

// -------------------- prep kernels --------------------
__global__ __launch_bounds__(256) void rownorm_split(const float* __restrict__ x,
                                                     const float* __restrict__ gptr)
{
    int row  = blockIdx.x * 8 + (threadIdx.x >> 5);
    int lane = threadIdx.x & 31;
    const float* xr = x + (size_t)row * DD;
    float vbuf[16];
    float s = 0.f;
#pragma unroll
    for (int t = 0; t < 16; t++) {
        vbuf[t] = xr[lane + 32 * t];
        s = fmaf(vbuf[t], vbuf[t], s);
    }
#pragma unroll
    for (int o = 16; o; o >>= 1) s += __shfl_xor_sync(0xffffffffu, s, o);
    float sc = gptr[0] / fmaxf(sqrtf(s), 1e-5f);
#pragma unroll
    for (int t = 0; t < 16; t++) {
        fp16 h, l; split2h(vbuf[t] * sc, h, l);
        size_t idx = (size_t)row * DD + lane + 32 * t;
        g_xs_h[idx] = h;
        g_xs_l[idx] = l;
    }
}
// W=0: uvwt[c][r] = fp16(uv_w[r][c]);  W=1: owt[d][e] = fp16(o_w[e][d])
template<int W>
__global__ __launch_bounds__(256) void wsplit(const float* __restrict__ src)
{
    int id = blockIdx.x * 256 + threadIdx.x;
    if (W == 0) {
        if (id >= UVC * DD) return;
        int c = id / DD, r = id % DD;
        g_uvwt[id] = __float2half_rn(src[(size_t)r * UVC + c]);
    } else {
        if (id >= DD * EE) return;
        int e = id % EE, d = id / EE;
        g_owt[id] = __float2half_rn(src[(size_t)e * DD + d]);
    }
}

// ==========================================================================
// mma.sync fp16 2-term GEMM (A split hi/lo, B single), cp.async 1-barrier
// pipeline.  qk (MODE 1) stays 3-term (B also split) since relu^2 doubles
// its relative error.  128x128 CTA tile, 2 CTA/SM, 8 warps (2x4),
// warp 64x32 = 4x4 m16n8k16 grid.
// MODE 0: uv (A=xs, B=uvwt, K=512)   epi: silu -> u / vt(staged) / q,k
// MODE 1: qk (A=q,  B=k,    K=128)   epi: +bias, relu^2/sqrtS -> attn
// MODE 2: av (A=attn, B=vt, K=1024)  epi: u-gate -> mid
// MODE 3: fin(A=mid,  B=owt,K=1024)  epi: residual -> out
// ==========================================================================
#define LDA      40                      // elems per smem row (80 B, conflict-free)
#define PLANE_BY (128 * LDA * 2)         // 10240

template<int MODE>
__global__ __launch_bounds__(256, 2) void gemm15(
    const float* __restrict__ e0, const float* __restrict__ e1, float* __restrict__ outp)
{
    constexpr int K      = (MODE == 0) ? DD : (MODE == 1) ? SS : NN;
    constexpr int CHUNKS = K / 32;
    constexpr int NPL    = (MODE == 1) ? 4 : 3;     // Ah, Al, Bh[, Bl]
    constexpr int BUF_BY = NPL * PLANE_BY;

    extern __shared__ char smem[];
    const uint32_t sbase = smem_u32(smem);
    const int tid = threadIdx.x, wid = tid >> 5, lane = tid & 31;
    const int warp_m = wid >> 2, warp_n = wid & 3;
    const int bx = blockIdx.x, b = blockIdx.z;
    const int row0 = blockIdx.y * 128, col0 = bx * 128;

    const fp16 *planes[4] = {nullptr, nullptr, nullptr, nullptr};
    if (MODE == 0) { planes[0] = g_xs_h;   planes[1] = g_xs_l;  planes[2] = g_uvwt; }
    if (MODE == 1) { planes[0] = g_q_h + (size_t)b * NN * SS;  planes[1] = g_q_l + (size_t)b * NN * SS;
                     planes[2] = g_k_h + (size_t)b * NN * SS;  planes[3] = g_k_l + (size_t)b * NN * SS; }
    if (MODE == 2) { planes[0] = g_attn_h + (size_t)b * NN * NN; planes[1] = g_attn_l + (size_t)b * NN * NN;
                     planes[2] = g_vt + (size_t)b * EE * NN; }
    if (MODE == 3) { planes[0] = g_mid_h;  planes[1] = g_mid_l;  planes[2] = g_owt; }

    // per-thread cp.async coords: 2 x 16B per plane
    const int lr0 = tid >> 2, lc0 = tid & 3;
    const int lr1 = lr0 + 64;

    float acc[4][4][4];
#pragma unroll
    for (int i = 0; i < 4; i++)
#pragma unroll
        for (int j = 0; j < 4; j++)
#pragma unroll
            for (int e = 0; e < 4; e++) acc[i][j][e] = 0.f;

    auto load_chunk = [&](int c, int buf) {
        const uint32_t bo = sbase + buf * BUF_BY;
        const int k0 = c * 32;
#pragma unroll
        for (int p = 0; p < NPL; p++) {
            const fp16* src = planes[p] + k0;
            const int rbase = (p < 2) ? row0 : col0;
            CP16(bo + p * PLANE_BY + lr0 * 80 + lc0 * 16,
                 src + (size_t)(rbase + lr0) * K + lc0 * 8);
            CP16(bo + p * PLANE_BY + lr1 * 80 + lc0 * 16,
                 src + (size_t)(rbase + lr1) * K + lc0 * 8);
        }
        CP_COMMIT();
    };

    load_chunk(0, 0);

    for (int c = 0; c < CHUNKS; c++) {
        CP_WAIT(0);            // chunk c's loads (only pending group) complete
        __syncthreads();       // also proves all warps done reading buffer (c+1)&1
        if (c + 1 < CHUNKS) load_chunk(c + 1, (c + 1) & 1);   // overlaps compute below

        const uint32_t bo = sbase + (c & 1) * BUF_BY;
        const uint32_t uAh = bo, uAl = bo + PLANE_BY;
        const uint32_t uBh = bo + 2 * PLANE_BY, uBl = bo + 3 * PLANE_BY;

#pragma unroll
        for (int ks = 0; ks < 32; ks += 16) {
            // B fragments (hi; +lo only for MODE1)
            uint32_t bhi[4][2], blo[4][2];
#pragma unroll
            for (int p = 0; p < 2; p++) {
                int n = warp_n * 32 + p * 16 + (lane & 7) + ((lane >> 4) << 3);
                uint32_t off = (uint32_t)(n * LDA + ks + (((lane >> 3) & 1) << 3)) * 2;
                uint32_t r4[4];
                ldsm_x4(r4, uBh + off);
                bhi[2*p][0] = r4[0]; bhi[2*p][1] = r4[1];
                bhi[2*p+1][0] = r4[2]; bhi[2*p+1][1] = r4[3];
                if (MODE == 1) {
                    ldsm_x4(r4, uBl + off);
                    blo[2*p][0] = r4[0]; blo[2*p][1] = r4[1];
                    blo[2*p+1][0] = r4[2]; blo[2*p+1][1] = r4[3];
                }
            }
#pragma unroll
            for (int mt = 0; mt < 4; mt++) {
                int m = warp_m * 64 + mt * 16 + (lane & 15);
                uint32_t off = (uint32_t)(m * LDA + ks + ((lane >> 4) << 3)) * 2;
                uint32_t ahi[4], alo[4];
                ldsm_x4(ahi, uAh + off);
                ldsm_x4(alo, uAl + off);
#pragma unroll
                for (int nt = 0; nt < 4; nt++) {
                    mma_f16(acc[mt][nt], ahi, bhi[nt]);
                    mma_f16(acc[mt][nt], alo, bhi[nt]);
                    if (MODE == 1) mma_f16(acc[mt][nt], ahi, blo[nt]);
                }
            }
        }
        // no trailing barrier: next iteration's barrier provides the guarantee
    }

    // -------------------- epilogue --------------------
    const float inv_sqrt_s = 0.088388347648318447f;   // 1/sqrt(128)
    fp16* stH = (fp16*)smem;                          // v-transpose staging (aliased)
    if (MODE == 0) __syncthreads();                   // staging aliases pipeline buffers

#pragma unroll
    for (int mt = 0; mt < 4; mt++) {
#pragma unroll
        for (int nt = 0; nt < 4; nt++) {
            int mb = row0 + warp_m * 64 + mt * 16 + (lane >> 2);
            int nb = col0 + warp_n * 32 + nt * 8 + ((lane & 3) << 1);
#pragma unroll
            for (int h = 0; h < 2; h++) {
                int m = mb + 8 * h;
                int n = nb;
                float v0 = acc[mt][nt][h * 2 + 0];
                float v1 = acc[mt][nt][h * 2 + 1];
                if (MODE == 0) {
                    float s0 = v0 / (1.f + __expf(-v0));
                    float s1 = v1 / (1.f + __expf(-v1));
                    if (bx < 8) {                      // u (fp32)
                        *(float2*)(g_u + (size_t)m * EE + n) = make_float2(s0, s1);
                    } else if (bx < 16) {              // v -> stage transposed (single)
                        int nl = n - col0, ml = m - row0;
                        stH[nl * 136 + ml] = __float2half_rn(s0);
                        stH[(nl + 1) * 136 + ml] = __float2half_rn(s1);
                    } else {                           // q,k split fp16
                        int s = n - 2 * EE;
                        uint32_t lo, hi;
                        size_t o = (size_t)m * SS + s;
                        hi = pksplit_h(fmaf(s0, e0[s], e1[s]), fmaf(s1, e0[s + 1], e1[s + 1]), lo);
                        *(uint32_t*)(g_q_h + o) = hi; *(uint32_t*)(g_q_l + o) = lo;
                        hi = pksplit_h(fmaf(s0, e0[SS + s], e1[SS + s]),
                                       fmaf(s1, e0[SS + s + 1], e1[SS + s + 1]), lo);
                        *(uint32_t*)(g_k_h + o) = hi; *(uint32_t*)(g_k_l + o) = lo;
                    }
                } else if (MODE == 1) {
                    float t0 = (v0 + e0[NN - 1 + n - m]) * inv_sqrt_s;     t0 = fmaxf(t0, 0.f);
                    float t1 = (v1 + e0[NN - 1 + n + 1 - m]) * inv_sqrt_s; t1 = fmaxf(t1, 0.f);
                    uint32_t lo, hi = pksplit_h(t0 * t0, t1 * t1, lo);
                    size_t o = ((size_t)b * NN + m) * NN + n;
                    *(uint32_t*)(g_attn_h + o) = hi;
                    *(uint32_t*)(g_attn_l + o) = lo;
                } else if (MODE == 2) {
                    size_t o = ((size_t)b * NN + m) * EE + n;
                    float2 uu = *(const float2*)(g_u + o);
                    uint32_t lo, hi = pksplit_h(uu.x * v0, uu.y * v1, lo);
                    *(uint32_t*)(g_mid_h + o) = hi;
                    *(uint32_t*)(g_mid_l + o) = lo;
                } else {
                    size_t o = (size_t)m * DD + n;
                    float2 xv = *(const float2*)(e0 + o);
                    *(float2*)(outp + o) = make_float2(fmaf(xv.x, e1[n], v0),
                                                       fmaf(xv.y, e1[n + 1], v1));
                }
            }
        }
    }

    // v-block: coalesced copy-out of staged transposed tile (single plane)
    if (MODE == 0 && bx >= 8 && bx < 16) {
        __syncthreads();
        const int bb = row0 >> 10, mloc = row0 & (NN - 1);
        const int ebase = col0 - EE;
#pragma unroll
        for (int it = 0; it < 8; it++) {
            int id = tid + 256 * it;
            int el = id >> 4, mw = id & 15;
            size_t o = ((size_t)bb * EE + ebase + el) * NN + mloc + mw * 8;
            *(uint4*)(g_vt + o) = *(const uint4*)&stH[el * 136 + mw * 8];
        }
    }
}

// -------------------- launch --------------------
extern "C" void kernel_launch(void* const* d_in, const int* in_sizes, int n_in,
                              void* d_out, int out_size)
{
    const float* x     = (const float*)d_in[0];
    const float* w     = (const float*)d_in[1];
    const float* uvw   = (const float*)d_in[2];
    const float* ow    = (const float*)d_in[3];
    const float* gamma = (const float*)d_in[4];
    const float* beta  = (const float*)d_in[5];
    const float* g     = (const float*)d_in[6];
    const float* res   = (const float*)d_in[7];
    float* out = (float*)d_out;

    const size_t smem3 = 2 * 3 * PLANE_BY;   // 61440
    const size_t smem4 = 2 * 4 * PLANE_BY;   // 81920

    cudaFuncSetAttribute(gemm15<0>, cudaFuncAttributeMaxDynamicSharedMemorySize, smem3);
    cudaFuncSetAttribute(gemm15<1>, cudaFuncAttributeMaxDynamicSharedMemorySize, smem4);
    cudaFuncSetAttribute(gemm15<2>, cudaFuncAttributeMaxDynamicSharedMemorySize, smem3);
    cudaFuncSetAttribute(gemm15<3>, cudaFuncAttributeMaxDynamicSharedMemorySize, smem3);

    rownorm_split<<<ROWS / 8, 256>>>(x, g);
    wsplit<0><<<(UVC * DD + 255) / 256, 256>>>(uvw);
    wsplit<1><<<(DD * EE + 255) / 256, 256>>>(ow);

    gemm15<0><<<dim3(UVC / 128, ROWS / 128, 1), 256, smem3>>>(gamma, beta, nullptr);
    gemm15<1><<<dim3(NN / 128, NN / 128, NB),   256, smem4>>>(w, nullptr, nullptr);
    gemm15<2><<<dim3(EE / 128, NN / 128, NB),   256, smem3>>>(nullptr, nullptr, nullptr);
    gemm15<3><<<dim3(DD / 128, ROWS / 128, 1),  256, smem3>>>(x, res, out);
}